// round 8
// baseline (speedup 1.0000x reference)
#include <cuda_runtime.h>
#include <cuda_fp16.h>
#include <math.h>
#include <stdint.h>

#define C_DIM 256
#define M_DIM 196
#define BATCH 256
#define TRIU_LEN 32896  // 256*257/2
#define PLANE 65536     // elems per half-plane (256x256)
#define XCOLS 208       // x cols padded to 13*16
#define XPLANE (256 * XCOLS)

#define NSTAGE 3
#define TILEB 4096      // 128 rows x 32B (16 halves)

// ---------------------------------------------------------------------------
// Scratch (allocation-free: __device__ globals). All intermediates live as
// fp16 hi/lo plane pairs: [batch][hi|lo][256][256].
// ---------------------------------------------------------------------------
__device__ __half g_A2 [BATCH * 2 * PLANE];
__device__ __half g_Y2 [BATCH * 2 * PLANE];
__device__ __half g_Z2 [BATCH * 2 * PLANE];
__device__ __half g_ZY2[BATCH * 2 * PLANE];
__device__ __half g_T2 [BATCH * 2 * PLANE];
__device__ __half g_X2 [BATCH * 2 * XPLANE];
__device__ float g_mu[BATCH * C_DIM];
__device__ float g_norm[BATCH];

// ---------------------------------------------------------------------------
// PTX helpers (plain sm_103-legal: ldmatrix / mma.sync / cp.async)
// ---------------------------------------------------------------------------
__device__ __forceinline__ void ldmx4(uint32_t* r, uint32_t saddr) {
    asm volatile("ldmatrix.sync.aligned.m8n8.x4.shared.b16 {%0,%1,%2,%3}, [%4];"
                 : "=r"(r[0]), "=r"(r[1]), "=r"(r[2]), "=r"(r[3])
                 : "r"(saddr));
}

__device__ __forceinline__ void mma16816(float* c, const uint32_t* a,
                                         uint32_t b0, uint32_t b1) {
    asm volatile(
        "mma.sync.aligned.m16n8k16.row.col.f32.f16.f16.f32 "
        "{%0,%1,%2,%3}, {%4,%5,%6,%7}, {%8,%9}, {%0,%1,%2,%3};"
        : "+f"(c[0]), "+f"(c[1]), "+f"(c[2]), "+f"(c[3])
        : "r"(a[0]), "r"(a[1]), "r"(a[2]), "r"(a[3]), "r"(b0), "r"(b1));
}

__device__ __forceinline__ void cp16(uint32_t saddr, const void* gaddr) {
    asm volatile("cp.async.cg.shared.global [%0], [%1], 16;"
                 :: "r"(saddr), "l"(gaddr) : "memory");
}
#define CP_COMMIT() asm volatile("cp.async.commit_group;" ::: "memory")
#define CP_WAIT2()  asm volatile("cp.async.wait_group 2;" ::: "memory")
#define CP_WAIT1()  asm volatile("cp.async.wait_group 1;" ::: "memory")
#define CP_WAIT0()  asm volatile("cp.async.wait_group 0;" ::: "memory")

__device__ __forceinline__ uint32_t packh(__half a, __half b) {
    return (uint32_t)__half_as_ushort(a) | ((uint32_t)__half_as_ushort(b) << 16);
}

__device__ __forceinline__ void split1(float v, __half& h, __half& l) {
    h = __float2half_rn(v);
    l = __float2half_rn(v - __half2float(h));
}

// XOR-swizzled tile offset: 128 rows x 2 chunks of 16B, conflict-free ldmatrix
__device__ __forceinline__ uint32_t sw_off(int row, int chunk) {
    return (uint32_t)(row * 32 + ((chunk ^ (row >> 2)) & 1) * 16);
}
__device__ __forceinline__ uint32_t frag_addr(uint32_t tilebase, int baserow, int lane) {
    int row = baserow + (lane & 15);
    int chunk = (lane >> 4) & 1;
    return tilebase + sw_off(row, chunk);
}

// ---------------------------------------------------------------------------
// Stats: per-channel mean + normA = trace(cov)
// ---------------------------------------------------------------------------
__global__ void stats_kernel(const float* __restrict__ x) {
    int b = blockIdx.x;
    int c = threadIdx.x;
    const float* xp = x + ((size_t)b * C_DIM + c) * M_DIM;
    float s = 0.f, s2 = 0.f;
#pragma unroll 4
    for (int m = 0; m < M_DIM; m++) {
        float v = xp[m];
        s += v;
        s2 += v * v;
    }
    float mu = s * (1.0f / M_DIM);
    g_mu[b * C_DIM + c] = mu;
    float contrib = s2 * (1.0f / M_DIM) - mu * mu;

    __shared__ float red[C_DIM];
    red[c] = contrib;
    __syncthreads();
    for (int off = C_DIM / 2; off > 0; off >>= 1) {
        if (c < off) red[c] += red[c + off];
        __syncthreads();
    }
    if (c == 0) g_norm[b] = red[0];
}

// ---------------------------------------------------------------------------
// Split x into fp16 hi/lo planes, padded to XCOLS. Warp per (b, channel) row.
// ---------------------------------------------------------------------------
__global__ void split_x_kernel(const float* __restrict__ x) {
    int gw = (blockIdx.x * blockDim.x + threadIdx.x) >> 5;
    int lane = threadIdx.x & 31;
    int b = gw >> 8, c = gw & 255;
    const float* xp = x + ((size_t)b * C_DIM + c) * M_DIM;
    __half* xh = g_X2 + (size_t)b * 2 * XPLANE + (size_t)c * XCOLS;
    __half* xl = xh + XPLANE;
    for (int m = lane; m < XCOLS; m += 32) {
        float v = (m < M_DIM) ? xp[m] : 0.f;
        __half h, l;
        split1(v, h, l);
        xh[m] = h;
        xl[m] = l;
    }
}

// ---------------------------------------------------------------------------
// GEMM core: 128x128 tile, 8 warps (2x4), warp tile 64x32, 3-stage cp.async
// pipeline (issue hoisted ABOVE the wait -> 2-stage latency cover that does
// not couple to wait stalls), 3xFP16-split mma.sync.
// MODE: 0 plain->halves(+mirror), 1: 1.5I-0.5acc->halves(+mirror),
//       2: triu(acc*sqrt(norm))->fp32 out, 3: covariance epilogue.
// ---------------------------------------------------------------------------
template <int MODE, int NC>
__device__ __forceinline__ void gemm_core(const __half* __restrict__ Ah,
                                          const __half* __restrict__ Al,
                                          const __half* __restrict__ Bh,
                                          const __half* __restrict__ Bl,
                                          int stride,
                                          __half* __restrict__ Ch,   // hi plane (lo at +PLANE)
                                          float* __restrict__ outF,
                                          int b, int ti0, int tj0, bool mirror) {
    __shared__ __align__(16) char smem[NSTAGE][4][TILEB];

    int tid = threadIdx.x, lane = tid & 31, wid = tid >> 5;
    int wr = wid >> 2, wc = wid & 3;

    // cp.async loader mapping: thread -> (row, chunk); 1 cp per tile per thread
    int lrow = tid >> 1, lchunk = tid & 1;
    uint32_t ldst = sw_off(lrow, lchunk);
    size_t lsrc = (size_t)lrow * stride + lchunk * 8;

    const __half* srcs[4] = {Ah, Al, Bh, Bl};

    auto issue = [&](int kc) {
        int s = kc % NSTAGE;
        int k0 = kc * 16;
#pragma unroll
        for (int t = 0; t < 4; t++) {
            uint32_t sa = (uint32_t)__cvta_generic_to_shared(&smem[s][t][0]) + ldst;
            cp16(sa, srcs[t] + lsrc + k0);
        }
        CP_COMMIT();
    };

    issue(0);
    issue(1);

    float acc[4][4][4] = {};

#pragma unroll 1
    for (int kc = 0; kc < NC; kc++) {
        // Issue the next group BEFORE waiting: a wait-stall must not delay
        // future issues (R7 flaw). Stage (kc+2)%3 was last read in iter kc-1,
        // protected by its trailing sync.
        if (kc + 2 < NC) issue(kc + 2);
        // Ensure group kc has completed. Outstanding groups are kc..min(kc+2,NC-1).
        int rem = NC - 1 - kc;
        if (rem >= 2) { CP_WAIT2(); } else if (rem == 1) { CP_WAIT1(); } else { CP_WAIT0(); }
        __syncthreads();

        int s = kc % NSTAGE;
        uint32_t abase_h = (uint32_t)__cvta_generic_to_shared(&smem[s][0][0]);
        uint32_t abase_l = (uint32_t)__cvta_generic_to_shared(&smem[s][1][0]);
        uint32_t bbase_h = (uint32_t)__cvta_generic_to_shared(&smem[s][2][0]);
        uint32_t bbase_l = (uint32_t)__cvta_generic_to_shared(&smem[s][3][0]);

        uint32_t Bh8[8], Bl8[8];
#pragma unroll
        for (int bj = 0; bj < 2; bj++) {
            ldmx4(&Bh8[4 * bj], frag_addr(bbase_h, wc * 32 + bj * 16, lane));
            ldmx4(&Bl8[4 * bj], frag_addr(bbase_l, wc * 32 + bj * 16, lane));
        }
#pragma unroll
        for (int fi = 0; fi < 4; fi++) {
            uint32_t Ah4[4], Al4[4];
            ldmx4(Ah4, frag_addr(abase_h, wr * 64 + fi * 16, lane));
            ldmx4(Al4, frag_addr(abase_l, wr * 64 + fi * 16, lane));
#pragma unroll
            for (int fj = 0; fj < 4; fj++) {
                int bj = fj >> 1, o = fj & 1;
                mma16816(acc[fi][fj], Ah4, Bh8[4 * bj + o], Bh8[4 * bj + 2 + o]);
                mma16816(acc[fi][fj], Ah4, Bl8[4 * bj + o], Bl8[4 * bj + 2 + o]);
                mma16816(acc[fi][fj], Al4, Bh8[4 * bj + o], Bh8[4 * bj + 2 + o]);
            }
        }
        __syncthreads();
    }

    // ------------------------- epilogue -------------------------
    int g = lane >> 2, t = lane & 3;

    if (MODE == 2) {
        float sc = sqrtf(g_norm[b]);
        float* outb = outF + (size_t)b * TRIU_LEN;
#pragma unroll
        for (int fi = 0; fi < 4; fi++) {
#pragma unroll
            for (int fj = 0; fj < 4; fj++) {
                int gi0 = ti0 + wr * 64 + fi * 16 + g;
                int gj0 = tj0 + wc * 32 + fj * 8 + 2 * t;
#pragma unroll
                for (int h = 0; h < 2; h++) {
                    int gi = gi0 + h * 8;
                    int rowbase = gi * C_DIM - (gi * (gi - 1)) / 2 - gi;
                    float v0 = acc[fi][fj][2 * h] * sc;
                    float v1 = acc[fi][fj][2 * h + 1] * sc;
                    if (gj0 >= gi)     outb[rowbase + gj0]     = v0;
                    if (gj0 + 1 >= gi) outb[rowbase + gj0 + 1] = v1;
                }
            }
        }
        return;
    }

    const float* mub = g_mu + b * C_DIM;
    float rn = (MODE == 3) ? (1.0f / g_norm[b]) : 0.f;
    __half* Cl = Ch + PLANE;
    __half* Zh = g_Z2 + (size_t)b * 2 * PLANE;   // MODE 3 second output
    __half* Zl = Zh + PLANE;

#pragma unroll
    for (int fi = 0; fi < 4; fi++) {
#pragma unroll
        for (int fj = 0; fj < 4; fj++) {
            int gi0 = ti0 + wr * 64 + fi * 16 + g;
            int gj0 = tj0 + wc * 32 + fj * 8 + 2 * t;
#pragma unroll
            for (int h = 0; h < 2; h++) {
                int gi = gi0 + h * 8;
                float r0 = acc[fi][fj][2 * h], r1 = acc[fi][fj][2 * h + 1];
                if (MODE == 3) {
                    float mi = mub[gi];
                    float v0 = (r0 * (1.0f / M_DIM) - mi * mub[gj0])     * rn;
                    float v1 = (r1 * (1.0f / M_DIM) - mi * mub[gj0 + 1]) * rn;
                    float z0 = (gi == gj0     ? 1.5f : 0.0f) - 0.5f * v0;
                    float z1 = (gi == gj0 + 1 ? 1.5f : 0.0f) - 0.5f * v1;
                    __half vh0, vl0, vh1, vl1, zh0, zl0, zh1, zl1;
                    split1(v0, vh0, vl0); split1(v1, vh1, vl1);
                    split1(z0, zh0, zl0); split1(z1, zh1, zl1);
                    *(uint32_t*)&Ch[gi * C_DIM + gj0] = packh(vh0, vh1);
                    *(uint32_t*)&Cl[gi * C_DIM + gj0] = packh(vl0, vl1);
                    *(uint32_t*)&Zh[gi * C_DIM + gj0] = packh(zh0, zh1);
                    *(uint32_t*)&Zl[gi * C_DIM + gj0] = packh(zl0, zl1);
                    if (mirror) {
                        Ch[gj0 * C_DIM + gi] = vh0; Cl[gj0 * C_DIM + gi] = vl0;
                        Ch[(gj0 + 1) * C_DIM + gi] = vh1; Cl[(gj0 + 1) * C_DIM + gi] = vl1;
                        Zh[gj0 * C_DIM + gi] = zh0; Zl[gj0 * C_DIM + gi] = zl0;
                        Zh[(gj0 + 1) * C_DIM + gi] = zh1; Zl[(gj0 + 1) * C_DIM + gi] = zl1;
                    }
                } else {
                    float v0 = (MODE == 1) ? ((gi == gj0     ? 1.5f : 0.0f) - 0.5f * r0) : r0;
                    float v1 = (MODE == 1) ? ((gi == gj0 + 1 ? 1.5f : 0.0f) - 0.5f * r1) : r1;
                    __half h0, l0, h1, l1;
                    split1(v0, h0, l0); split1(v1, h1, l1);
                    *(uint32_t*)&Ch[gi * C_DIM + gj0] = packh(h0, h1);
                    *(uint32_t*)&Cl[gi * C_DIM + gj0] = packh(l0, l1);
                    if (mirror) {
                        Ch[gj0 * C_DIM + gi] = h0; Cl[gj0 * C_DIM + gi] = l0;
                        Ch[(gj0 + 1) * C_DIM + gi] = h1; Cl[(gj0 + 1) * C_DIM + gi] = l1;
                    }
                }
            }
        }
    }
}

// ---------------------------------------------------------------------------
// Kernels (symmetric 3-tile grid: bx 0=(0,0), 1=(0,1) mirrored, 2=(1,1))
// ---------------------------------------------------------------------------
__global__ __launch_bounds__(256) void cov_kernel() {
    int bx = blockIdx.x, b = blockIdx.z;
    int ti0 = (bx == 2) ? 128 : 0;
    int tj0 = (bx >= 1) ? 128 : 0;
    const __half* Xh = g_X2 + (size_t)b * 2 * XPLANE;
    const __half* Xl = Xh + XPLANE;
    gemm_core<3, 13>(Xh + (size_t)ti0 * XCOLS, Xl + (size_t)ti0 * XCOLS,
                     Xh + (size_t)tj0 * XCOLS, Xl + (size_t)tj0 * XCOLS,
                     XCOLS,
                     g_A2 + (size_t)b * 2 * PLANE, nullptr,
                     b, ti0, tj0, bx == 1);
}

template <int MODE>
__global__ __launch_bounds__(256) void ns_gemm(const __half* __restrict__ A,
                                               const __half* __restrict__ B,
                                               __half* __restrict__ C,
                                               float* __restrict__ outF) {
    int bx = blockIdx.x, b = blockIdx.z;
    int ti0 = (bx == 2) ? 128 : 0;
    int tj0 = (bx >= 1) ? 128 : 0;
    const __half* Ah = A + (size_t)b * 2 * PLANE + (size_t)ti0 * C_DIM;
    const __half* Bh = B + (size_t)b * 2 * PLANE + (size_t)tj0 * C_DIM;
    gemm_core<MODE, 16>(Ah, Ah + PLANE, Bh, Bh + PLANE, C_DIM,
                        (MODE == 2) ? nullptr : C + (size_t)b * 2 * PLANE, outF,
                        b, ti0, tj0, bx == 1);
}

__global__ __launch_bounds__(256) void ns_gemm_dual(
    const __half* __restrict__ A1, const __half* __restrict__ B1, __half* __restrict__ C1,
    const __half* __restrict__ A2, const __half* __restrict__ B2, __half* __restrict__ C2) {
    int bx = blockIdx.x, b = blockIdx.z;
    int ti0 = (bx == 2) ? 128 : 0;
    int tj0 = (bx >= 1) ? 128 : 0;
    const __half* A = (blockIdx.y == 0) ? A1 : A2;
    const __half* B = (blockIdx.y == 0) ? B1 : B2;
    __half* C = (blockIdx.y == 0) ? C1 : C2;
    const __half* Ah = A + (size_t)b * 2 * PLANE + (size_t)ti0 * C_DIM;
    const __half* Bh = B + (size_t)b * 2 * PLANE + (size_t)tj0 * C_DIM;
    gemm_core<0, 16>(Ah, Ah + PLANE, Bh, Bh + PLANE, C_DIM,
                     C + (size_t)b * 2 * PLANE, nullptr, b, ti0, tj0, bx == 1);
}

// ---------------------------------------------------------------------------
// Launch: Newton-Schulz (ITER_N = 3)
//   ZY0 = 1.5I - 0.5 Ahat; Y1 = Ahat@ZY0; Z1 = ZY0
//   ZY1 = 1.5I - 0.5 Z1@Y1; Y2 = Y1@ZY1; Z2 = ZY1@Z1
//   E   = 1.5I - 0.5 Z2@Y2; out = triu((Y2@E)*sqrt(normA))
// ---------------------------------------------------------------------------
extern "C" void kernel_launch(void* const* d_in, const int* in_sizes, int n_in,
                              void* d_out, int out_size) {
    const float* x = (const float*)d_in[0];
    float* out = (float*)d_out;

    __half *A2, *Y2, *Z2, *ZY2, *T2;
    cudaGetSymbolAddress((void**)&A2,  g_A2);
    cudaGetSymbolAddress((void**)&Y2,  g_Y2);
    cudaGetSymbolAddress((void**)&Z2,  g_Z2);
    cudaGetSymbolAddress((void**)&ZY2, g_ZY2);
    cudaGetSymbolAddress((void**)&T2,  g_T2);

    dim3 grid(3, 1, BATCH), grid2(3, 2, BATCH);

    stats_kernel<<<BATCH, C_DIM>>>(x);
    split_x_kernel<<<BATCH * 256 / 8, 256>>>(x);
    cov_kernel<<<grid, 256>>>();                         // g_A2 = Ahat, g_Z2 = ZY0
    ns_gemm<0><<<grid, 256>>>(A2, Z2, Y2, nullptr);      // Y1 = Ahat @ ZY0
    ns_gemm<1><<<grid, 256>>>(Z2, Y2, ZY2, nullptr);     // ZY1 = 1.5I - 0.5 Z1@Y1
    ns_gemm_dual<<<grid2, 256>>>(Y2, ZY2, A2,            // Y2 = Y1 @ ZY1
                                 ZY2, Z2, T2);           // Z2 = ZY1 @ Z1
    ns_gemm<1><<<grid, 256>>>(T2, A2, ZY2, nullptr);     // E = 1.5I - 0.5 Z2@Y2
    ns_gemm<2><<<grid, 256>>>(A2, ZY2, nullptr, out);    // out = triu((Y2@E)*sqrt)
}

// round 9
// speedup vs baseline: 1.0480x; 1.0480x over previous
#include <cuda_runtime.h>
#include <cuda_fp16.h>
#include <math.h>
#include <stdint.h>

#define C_DIM 256
#define M_DIM 196
#define BATCH 256
#define TRIU_LEN 32896  // 256*257/2
#define PLANE 65536     // elems per half-plane (256x256)
#define XCOLS 208       // x cols padded to 13*16 (zero-filled -> no k guards)
#define XPLANE (256 * XCOLS)

#define TILEB 4096      // one stage-plane tile: 128 rows x 32B (16 halves)

// ---------------------------------------------------------------------------
// Scratch (allocation-free: __device__ globals). All intermediates live as
// fp16 hi/lo plane pairs: [batch][hi|lo][256][256].
// ---------------------------------------------------------------------------
__device__ __half g_A2 [BATCH * 2 * PLANE];
__device__ __half g_Y2 [BATCH * 2 * PLANE];
__device__ __half g_Z2 [BATCH * 2 * PLANE];
__device__ __half g_ZY2[BATCH * 2 * PLANE];
__device__ __half g_T2 [BATCH * 2 * PLANE];
__device__ __half g_X2 [BATCH * 2 * XPLANE];
__device__ float g_mu[BATCH * C_DIM];
__device__ float g_norm[BATCH];

// ---------------------------------------------------------------------------
// PTX helpers (plain sm_103-legal: ldmatrix / mma.sync)
// ---------------------------------------------------------------------------
__device__ __forceinline__ void ldmx4(uint32_t* r, uint32_t saddr) {
    asm volatile("ldmatrix.sync.aligned.m8n8.x4.shared.b16 {%0,%1,%2,%3}, [%4];"
                 : "=r"(r[0]), "=r"(r[1]), "=r"(r[2]), "=r"(r[3])
                 : "r"(saddr));
}

__device__ __forceinline__ void mma16816(float* c, const uint32_t* a,
                                         uint32_t b0, uint32_t b1) {
    asm volatile(
        "mma.sync.aligned.m16n8k16.row.col.f32.f16.f16.f32 "
        "{%0,%1,%2,%3}, {%4,%5,%6,%7}, {%8,%9}, {%0,%1,%2,%3};"
        : "+f"(c[0]), "+f"(c[1]), "+f"(c[2]), "+f"(c[3])
        : "r"(a[0]), "r"(a[1]), "r"(a[2]), "r"(a[3]), "r"(b0), "r"(b1));
}

__device__ __forceinline__ uint32_t packh(__half a, __half b) {
    return (uint32_t)__half_as_ushort(a) | ((uint32_t)__half_as_ushort(b) << 16);
}

__device__ __forceinline__ void split1(float v, __half& h, __half& l) {
    h = __float2half_rn(v);
    l = __float2half_rn(v - __half2float(h));
}

// XOR-swizzled tile offset: 128 rows x 2 chunks of 16B, conflict-free ldmatrix
__device__ __forceinline__ uint32_t sw_off(int row, int chunk) {
    return (uint32_t)(row * 32 + ((chunk ^ (row >> 2)) & 1) * 16);
}
__device__ __forceinline__ uint32_t frag_addr(uint32_t tilebase, int baserow, int lane) {
    int row = baserow + (lane & 15);
    int chunk = (lane >> 4) & 1;
    return tilebase + sw_off(row, chunk);
}

// ---------------------------------------------------------------------------
// Stats: per-channel mean + normA = trace(cov)
// ---------------------------------------------------------------------------
__global__ void stats_kernel(const float* __restrict__ x) {
    int b = blockIdx.x;
    int c = threadIdx.x;
    const float* xp = x + ((size_t)b * C_DIM + c) * M_DIM;
    float s = 0.f, s2 = 0.f;
#pragma unroll 4
    for (int m = 0; m < M_DIM; m++) {
        float v = xp[m];
        s += v;
        s2 += v * v;
    }
    float mu = s * (1.0f / M_DIM);
    g_mu[b * C_DIM + c] = mu;
    float contrib = s2 * (1.0f / M_DIM) - mu * mu;

    __shared__ float red[C_DIM];
    red[c] = contrib;
    __syncthreads();
    for (int off = C_DIM / 2; off > 0; off >>= 1) {
        if (c < off) red[c] += red[c + off];
        __syncthreads();
    }
    if (c == 0) g_norm[b] = red[0];
}

// ---------------------------------------------------------------------------
// Split x into fp16 hi/lo planes, zero-padded to XCOLS. Warp per (b, c) row.
// ---------------------------------------------------------------------------
__global__ void split_x_kernel(const float* __restrict__ x) {
    int gw = (blockIdx.x * blockDim.x + threadIdx.x) >> 5;
    int lane = threadIdx.x & 31;
    int b = gw >> 8, c = gw & 255;
    const float* xp = x + ((size_t)b * C_DIM + c) * M_DIM;
    __half* xh = g_X2 + (size_t)b * 2 * XPLANE + (size_t)c * XCOLS;
    __half* xl = xh + XPLANE;
    for (int m = lane; m < XCOLS; m += 32) {
        float v = (m < M_DIM) ? xp[m] : 0.f;
        __half h, l;
        split1(v, h, l);
        xh[m] = h;
        xl[m] = l;
    }
}

// ---------------------------------------------------------------------------
// GEMM core: 128x128 tile, 8 warps (2x4), warp tile 64x32.
// R5-style pipeline: LDG->reg prefetch of stage kc+1 at loop top (per-warp
// scoreboards, no L1tex queue coupling), compute stage kc, STS prefetched
// data, ONE __syncthreads per stage. fp16 hi/lo planes: no in-loop converts.
// MODE: 0 plain->halves(+mirror), 1: 1.5I-0.5acc->halves(+mirror),
//       2: triu(acc*sqrt(norm))->fp32 out, 3: covariance epilogue.
// ---------------------------------------------------------------------------
template <int MODE, int NC>
__device__ __forceinline__ void gemm_core(const __half* __restrict__ Ah,
                                          const __half* __restrict__ Al,
                                          const __half* __restrict__ Bh,
                                          const __half* __restrict__ Bl,
                                          int stride,
                                          __half* __restrict__ Ch,   // hi plane (lo at +PLANE)
                                          float* __restrict__ outF,
                                          int b, int ti0, int tj0, bool mirror) {
    __shared__ __align__(16) char smem[2][4][TILEB];  // [stage][Ah,Al,Bh,Bl]

    int tid = threadIdx.x, lane = tid & 31, wid = tid >> 5;
    int wr = wid >> 2, wc = wid & 3;

    // loader mapping: thread -> (row, 16B chunk); one uint4 per tile per thread
    int lrow = tid >> 1, lchunk = tid & 1;
    uint32_t ldst = sw_off(lrow, lchunk);
    size_t lsrc = (size_t)lrow * stride + lchunk * 8;   // in halves

    const __half* srcs[4] = {Ah, Al, Bh, Bl};
    uint4 pref[4];

    // prologue: stage 0 straight to smem
#pragma unroll
    for (int t = 0; t < 4; t++) pref[t] = *(const uint4*)(srcs[t] + lsrc);
#pragma unroll
    for (int t = 0; t < 4; t++) *(uint4*)(&smem[0][t][0] + ldst) = pref[t];
    __syncthreads();

    float acc[4][4][4] = {};

#pragma unroll 1
    for (int kc = 0; kc < NC; kc++) {
        int s = kc & 1;
        // prefetch stage kc+1 into registers (covered by this stage's compute)
        if (kc + 1 < NC) {
            size_t o = lsrc + (size_t)(kc + 1) * 16;
#pragma unroll
            for (int t = 0; t < 4; t++) pref[t] = *(const uint4*)(srcs[t] + o);
        }

        uint32_t abase_h = (uint32_t)__cvta_generic_to_shared(&smem[s][0][0]);
        uint32_t abase_l = (uint32_t)__cvta_generic_to_shared(&smem[s][1][0]);
        uint32_t bbase_h = (uint32_t)__cvta_generic_to_shared(&smem[s][2][0]);
        uint32_t bbase_l = (uint32_t)__cvta_generic_to_shared(&smem[s][3][0]);

        uint32_t Bh8[8], Bl8[8];
#pragma unroll
        for (int bj = 0; bj < 2; bj++) {
            ldmx4(&Bh8[4 * bj], frag_addr(bbase_h, wc * 32 + bj * 16, lane));
            ldmx4(&Bl8[4 * bj], frag_addr(bbase_l, wc * 32 + bj * 16, lane));
        }
#pragma unroll
        for (int fi = 0; fi < 4; fi++) {
            uint32_t Ah4[4], Al4[4];
            ldmx4(Ah4, frag_addr(abase_h, wr * 64 + fi * 16, lane));
            ldmx4(Al4, frag_addr(abase_l, wr * 64 + fi * 16, lane));
#pragma unroll
            for (int fj = 0; fj < 4; fj++) {
                int bj = fj >> 1, o = fj & 1;
                mma16816(acc[fi][fj], Ah4, Bh8[4 * bj + o], Bh8[4 * bj + 2 + o]);
                mma16816(acc[fi][fj], Ah4, Bl8[4 * bj + o], Bl8[4 * bj + 2 + o]);
                mma16816(acc[fi][fj], Al4, Bh8[4 * bj + o], Bh8[4 * bj + 2 + o]);
            }
        }

        // store prefetched stage kc+1 into the other buffer; safe because the
        // trailing sync of iter kc-1 guaranteed everyone left that buffer.
        if (kc + 1 < NC) {
#pragma unroll
            for (int t = 0; t < 4; t++)
                *(uint4*)(&smem[s ^ 1][t][0] + ldst) = pref[t];
        }
        __syncthreads();
    }

    // ------------------------- epilogue -------------------------
    int g = lane >> 2, t = lane & 3;

    if (MODE == 2) {
        float sc = sqrtf(g_norm[b]);
        float* outb = outF + (size_t)b * TRIU_LEN;
#pragma unroll
        for (int fi = 0; fi < 4; fi++) {
#pragma unroll
            for (int fj = 0; fj < 4; fj++) {
                int gi0 = ti0 + wr * 64 + fi * 16 + g;
                int gj0 = tj0 + wc * 32 + fj * 8 + 2 * t;
#pragma unroll
                for (int h = 0; h < 2; h++) {
                    int gi = gi0 + h * 8;
                    int rowbase = gi * C_DIM - (gi * (gi - 1)) / 2 - gi;
                    float v0 = acc[fi][fj][2 * h] * sc;
                    float v1 = acc[fi][fj][2 * h + 1] * sc;
                    if (gj0 >= gi)     outb[rowbase + gj0]     = v0;
                    if (gj0 + 1 >= gi) outb[rowbase + gj0 + 1] = v1;
                }
            }
        }
        return;
    }

    const float* mub = g_mu + b * C_DIM;
    float rn = (MODE == 3) ? (1.0f / g_norm[b]) : 0.f;
    __half* Cl = Ch + PLANE;
    __half* Zh = g_Z2 + (size_t)b * 2 * PLANE;   // MODE 3 second output
    __half* Zl = Zh + PLANE;

#pragma unroll
    for (int fi = 0; fi < 4; fi++) {
#pragma unroll
        for (int fj = 0; fj < 4; fj++) {
            int gi0 = ti0 + wr * 64 + fi * 16 + g;
            int gj0 = tj0 + wc * 32 + fj * 8 + 2 * t;
#pragma unroll
            for (int h = 0; h < 2; h++) {
                int gi = gi0 + h * 8;
                float r0 = acc[fi][fj][2 * h], r1 = acc[fi][fj][2 * h + 1];
                if (MODE == 3) {
                    float mi = mub[gi];
                    float v0 = (r0 * (1.0f / M_DIM) - mi * mub[gj0])     * rn;
                    float v1 = (r1 * (1.0f / M_DIM) - mi * mub[gj0 + 1]) * rn;
                    float z0 = (gi == gj0     ? 1.5f : 0.0f) - 0.5f * v0;
                    float z1 = (gi == gj0 + 1 ? 1.5f : 0.0f) - 0.5f * v1;
                    __half vh0, vl0, vh1, vl1, zh0, zl0, zh1, zl1;
                    split1(v0, vh0, vl0); split1(v1, vh1, vl1);
                    split1(z0, zh0, zl0); split1(z1, zh1, zl1);
                    *(uint32_t*)&Ch[gi * C_DIM + gj0] = packh(vh0, vh1);
                    *(uint32_t*)&Cl[gi * C_DIM + gj0] = packh(vl0, vl1);
                    *(uint32_t*)&Zh[gi * C_DIM + gj0] = packh(zh0, zh1);
                    *(uint32_t*)&Zl[gi * C_DIM + gj0] = packh(zl0, zl1);
                    if (mirror) {
                        Ch[gj0 * C_DIM + gi] = vh0; Cl[gj0 * C_DIM + gi] = vl0;
                        Ch[(gj0 + 1) * C_DIM + gi] = vh1; Cl[(gj0 + 1) * C_DIM + gi] = vl1;
                        Zh[gj0 * C_DIM + gi] = zh0; Zl[gj0 * C_DIM + gi] = zl0;
                        Zh[(gj0 + 1) * C_DIM + gi] = zh1; Zl[(gj0 + 1) * C_DIM + gi] = zl1;
                    }
                } else {
                    float v0 = (MODE == 1) ? ((gi == gj0     ? 1.5f : 0.0f) - 0.5f * r0) : r0;
                    float v1 = (MODE == 1) ? ((gi == gj0 + 1 ? 1.5f : 0.0f) - 0.5f * r1) : r1;
                    __half h0, l0, h1, l1;
                    split1(v0, h0, l0); split1(v1, h1, l1);
                    *(uint32_t*)&Ch[gi * C_DIM + gj0] = packh(h0, h1);
                    *(uint32_t*)&Cl[gi * C_DIM + gj0] = packh(l0, l1);
                    if (mirror) {
                        Ch[gj0 * C_DIM + gi] = h0; Cl[gj0 * C_DIM + gi] = l0;
                        Ch[(gj0 + 1) * C_DIM + gi] = h1; Cl[(gj0 + 1) * C_DIM + gi] = l1;
                    }
                }
            }
        }
    }
}

// ---------------------------------------------------------------------------
// Kernels (symmetric 3-tile grid: bx 0=(0,0), 1=(0,1) mirrored, 2=(1,1))
// ---------------------------------------------------------------------------
__global__ __launch_bounds__(256) void cov_kernel() {
    int bx = blockIdx.x, b = blockIdx.z;
    int ti0 = (bx == 2) ? 128 : 0;
    int tj0 = (bx >= 1) ? 128 : 0;
    const __half* Xh = g_X2 + (size_t)b * 2 * XPLANE;
    const __half* Xl = Xh + XPLANE;
    gemm_core<3, 13>(Xh + (size_t)ti0 * XCOLS, Xl + (size_t)ti0 * XCOLS,
                     Xh + (size_t)tj0 * XCOLS, Xl + (size_t)tj0 * XCOLS,
                     XCOLS,
                     g_A2 + (size_t)b * 2 * PLANE, nullptr,
                     b, ti0, tj0, bx == 1);
}

template <int MODE>
__global__ __launch_bounds__(256) void ns_gemm(const __half* __restrict__ A,
                                               const __half* __restrict__ B,
                                               __half* __restrict__ C,
                                               float* __restrict__ outF) {
    int bx = blockIdx.x, b = blockIdx.z;
    int ti0 = (bx == 2) ? 128 : 0;
    int tj0 = (bx >= 1) ? 128 : 0;
    const __half* Ah = A + (size_t)b * 2 * PLANE + (size_t)ti0 * C_DIM;
    const __half* Bh = B + (size_t)b * 2 * PLANE + (size_t)tj0 * C_DIM;
    gemm_core<MODE, 16>(Ah, Ah + PLANE, Bh, Bh + PLANE, C_DIM,
                        (MODE == 2) ? nullptr : C + (size_t)b * 2 * PLANE, outF,
                        b, ti0, tj0, bx == 1);
}

__global__ __launch_bounds__(256) void ns_gemm_dual(
    const __half* __restrict__ A1, const __half* __restrict__ B1, __half* __restrict__ C1,
    const __half* __restrict__ A2, const __half* __restrict__ B2, __half* __restrict__ C2) {
    int bx = blockIdx.x, b = blockIdx.z;
    int ti0 = (bx == 2) ? 128 : 0;
    int tj0 = (bx >= 1) ? 128 : 0;
    const __half* A = (blockIdx.y == 0) ? A1 : A2;
    const __half* B = (blockIdx.y == 0) ? B1 : B2;
    __half* C = (blockIdx.y == 0) ? C1 : C2;
    const __half* Ah = A + (size_t)b * 2 * PLANE + (size_t)ti0 * C_DIM;
    const __half* Bh = B + (size_t)b * 2 * PLANE + (size_t)tj0 * C_DIM;
    gemm_core<0, 16>(Ah, Ah + PLANE, Bh, Bh + PLANE, C_DIM,
                     C + (size_t)b * 2 * PLANE, nullptr, b, ti0, tj0, bx == 1);
}

// ---------------------------------------------------------------------------
// Launch: Newton-Schulz (ITER_N = 3)
//   ZY0 = 1.5I - 0.5 Ahat; Y1 = Ahat@ZY0; Z1 = ZY0
//   ZY1 = 1.5I - 0.5 Z1@Y1; Y2 = Y1@ZY1; Z2 = ZY1@Z1
//   E   = 1.5I - 0.5 Z2@Y2; out = triu((Y2@E)*sqrt(normA))
// ---------------------------------------------------------------------------
extern "C" void kernel_launch(void* const* d_in, const int* in_sizes, int n_in,
                              void* d_out, int out_size) {
    const float* x = (const float*)d_in[0];
    float* out = (float*)d_out;

    __half *A2, *Y2, *Z2, *ZY2, *T2;
    cudaGetSymbolAddress((void**)&A2,  g_A2);
    cudaGetSymbolAddress((void**)&Y2,  g_Y2);
    cudaGetSymbolAddress((void**)&Z2,  g_Z2);
    cudaGetSymbolAddress((void**)&ZY2, g_ZY2);
    cudaGetSymbolAddress((void**)&T2,  g_T2);

    dim3 grid(3, 1, BATCH), grid2(3, 2, BATCH);

    stats_kernel<<<BATCH, C_DIM>>>(x);
    split_x_kernel<<<BATCH * 256 / 8, 256>>>(x);
    cov_kernel<<<grid, 256>>>();                         // g_A2 = Ahat, g_Z2 = ZY0
    ns_gemm<0><<<grid, 256>>>(A2, Z2, Y2, nullptr);      // Y1 = Ahat @ ZY0
    ns_gemm<1><<<grid, 256>>>(Z2, Y2, ZY2, nullptr);     // ZY1 = 1.5I - 0.5 Z1@Y1
    ns_gemm_dual<<<grid2, 256>>>(Y2, ZY2, A2,            // Y2 = Y1 @ ZY1
                                 ZY2, Z2, T2);           // Z2 = ZY1 @ Z1
    ns_gemm<1><<<grid, 256>>>(T2, A2, ZY2, nullptr);     // E = 1.5I - 0.5 Z2@Y2
    ns_gemm<2><<<grid, 256>>>(A2, ZY2, nullptr, out);    // out = triu((Y2@E)*sqrt)
}

// round 10
// speedup vs baseline: 1.0523x; 1.0041x over previous
#include <cuda_runtime.h>
#include <cuda_fp16.h>
#include <math.h>
#include <stdint.h>

#define C_DIM 256
#define M_DIM 196
#define BATCH 256
#define TRIU_LEN 32896  // 256*257/2
#define PLANE 65536     // elems per half-plane (256x256)
#define XCOLS 208       // x cols padded to 13*16 (zero-filled -> no k guards)
#define XPLANE (256 * XCOLS)

#define TILEB 4096      // one stage-plane tile: 128 rows x 32B (16 halves)

// ---------------------------------------------------------------------------
// Scratch (allocation-free: __device__ globals). All intermediates live as
// fp16 hi/lo plane pairs: [batch][hi|lo][256][256].
// ---------------------------------------------------------------------------
__device__ __half g_A2 [BATCH * 2 * PLANE];
__device__ __half g_Y2 [BATCH * 2 * PLANE];
__device__ __half g_Z2 [BATCH * 2 * PLANE];
__device__ __half g_ZY2[BATCH * 2 * PLANE];
__device__ __half g_T2 [BATCH * 2 * PLANE];
__device__ __half g_X2 [BATCH * 2 * XPLANE];
__device__ float g_mu[BATCH * C_DIM];
__device__ float g_norm[BATCH];

// ---------------------------------------------------------------------------
// PTX helpers (plain sm_103-legal: ldmatrix / mma.sync)
// ---------------------------------------------------------------------------
__device__ __forceinline__ void ldmx4(uint32_t* r, uint32_t saddr) {
    asm volatile("ldmatrix.sync.aligned.m8n8.x4.shared.b16 {%0,%1,%2,%3}, [%4];"
                 : "=r"(r[0]), "=r"(r[1]), "=r"(r[2]), "=r"(r[3])
                 : "r"(saddr));
}

__device__ __forceinline__ void mma16816(float* c, const uint32_t* a,
                                         uint32_t b0, uint32_t b1) {
    asm volatile(
        "mma.sync.aligned.m16n8k16.row.col.f32.f16.f16.f32 "
        "{%0,%1,%2,%3}, {%4,%5,%6,%7}, {%8,%9}, {%0,%1,%2,%3};"
        : "+f"(c[0]), "+f"(c[1]), "+f"(c[2]), "+f"(c[3])
        : "r"(a[0]), "r"(a[1]), "r"(a[2]), "r"(a[3]), "r"(b0), "r"(b1));
}

__device__ __forceinline__ uint32_t packh(__half a, __half b) {
    return (uint32_t)__half_as_ushort(a) | ((uint32_t)__half_as_ushort(b) << 16);
}

__device__ __forceinline__ void split1(float v, __half& h, __half& l) {
    h = __float2half_rn(v);
    l = __float2half_rn(v - __half2float(h));
}

// XOR-swizzled tile offset: 128 rows x 2 chunks of 16B, conflict-free ldmatrix
__device__ __forceinline__ uint32_t sw_off(int row, int chunk) {
    return (uint32_t)(row * 32 + ((chunk ^ (row >> 2)) & 1) * 16);
}
__device__ __forceinline__ uint32_t frag_addr(uint32_t tilebase, int baserow, int lane) {
    int row = baserow + (lane & 15);
    int chunk = (lane >> 4) & 1;
    return tilebase + sw_off(row, chunk);
}

// ---------------------------------------------------------------------------
// Stats: per-channel mean + normA = trace(cov)
// ---------------------------------------------------------------------------
__global__ void stats_kernel(const float* __restrict__ x) {
    int b = blockIdx.x;
    int c = threadIdx.x;
    const float* xp = x + ((size_t)b * C_DIM + c) * M_DIM;
    float s = 0.f, s2 = 0.f;
#pragma unroll 4
    for (int m = 0; m < M_DIM; m++) {
        float v = xp[m];
        s += v;
        s2 += v * v;
    }
    float mu = s * (1.0f / M_DIM);
    g_mu[b * C_DIM + c] = mu;
    float contrib = s2 * (1.0f / M_DIM) - mu * mu;

    __shared__ float red[C_DIM];
    red[c] = contrib;
    __syncthreads();
    for (int off = C_DIM / 2; off > 0; off >>= 1) {
        if (c < off) red[c] += red[c + off];
        __syncthreads();
    }
    if (c == 0) g_norm[b] = red[0];
}

// ---------------------------------------------------------------------------
// Split x into fp16 hi/lo planes, zero-padded to XCOLS. Warp per (b, c) row.
// ---------------------------------------------------------------------------
__global__ void split_x_kernel(const float* __restrict__ x) {
    int gw = (blockIdx.x * blockDim.x + threadIdx.x) >> 5;
    int lane = threadIdx.x & 31;
    int b = gw >> 8, c = gw & 255;
    const float* xp = x + ((size_t)b * C_DIM + c) * M_DIM;
    __half* xh = g_X2 + (size_t)b * 2 * XPLANE + (size_t)c * XCOLS;
    __half* xl = xh + XPLANE;
    for (int m = lane; m < XCOLS; m += 32) {
        float v = (m < M_DIM) ? xp[m] : 0.f;
        __half h, l;
        split1(v, h, l);
        xh[m] = h;
        xl[m] = l;
    }
}

// ---------------------------------------------------------------------------
// GEMM core: 128x128 tile, 8 warps (2x4), warp tile 64x32.
// LDG->reg prefetch pipeline (one sync/stage). Inner mma order is
// PRODUCT-MAJOR: all 4 independent-acc mmas of one split product issue
// before the next product touches the same accumulators (RAW distance 1->4;
// asm volatile means source order IS issue order, so this matters).
// MODE: 0 plain->halves(+mirror), 1: 1.5I-0.5acc->halves(+mirror),
//       2: triu(acc*sqrt(norm))->fp32 out, 3: covariance epilogue.
// ---------------------------------------------------------------------------
template <int MODE, int NC>
__device__ __forceinline__ void gemm_core(const __half* __restrict__ Ah,
                                          const __half* __restrict__ Al,
                                          const __half* __restrict__ Bh,
                                          const __half* __restrict__ Bl,
                                          int stride,
                                          __half* __restrict__ Ch,   // hi plane (lo at +PLANE)
                                          float* __restrict__ outF,
                                          int b, int ti0, int tj0, bool mirror) {
    __shared__ __align__(16) char smem[2][4][TILEB];  // [stage][Ah,Al,Bh,Bl]

    int tid = threadIdx.x, lane = tid & 31, wid = tid >> 5;
    int wr = wid >> 2, wc = wid & 3;

    // loader mapping: thread -> (row, 16B chunk); one uint4 per tile per thread
    int lrow = tid >> 1, lchunk = tid & 1;
    uint32_t ldst = sw_off(lrow, lchunk);
    size_t lsrc = (size_t)lrow * stride + lchunk * 8;   // in halves

    const __half* srcs[4] = {Ah, Al, Bh, Bl};
    uint4 pref[4];

    // prologue: stage 0 straight to smem
#pragma unroll
    for (int t = 0; t < 4; t++) pref[t] = *(const uint4*)(srcs[t] + lsrc);
#pragma unroll
    for (int t = 0; t < 4; t++) *(uint4*)(&smem[0][t][0] + ldst) = pref[t];
    __syncthreads();

    float acc[4][4][4] = {};

#pragma unroll 1
    for (int kc = 0; kc < NC; kc++) {
        int s = kc & 1;
        // prefetch stage kc+1 into registers (covered by this stage's compute)
        if (kc + 1 < NC) {
            size_t o = lsrc + (size_t)(kc + 1) * 16;
#pragma unroll
            for (int t = 0; t < 4; t++) pref[t] = *(const uint4*)(srcs[t] + o);
        }

        uint32_t abase_h = (uint32_t)__cvta_generic_to_shared(&smem[s][0][0]);
        uint32_t abase_l = (uint32_t)__cvta_generic_to_shared(&smem[s][1][0]);
        uint32_t bbase_h = (uint32_t)__cvta_generic_to_shared(&smem[s][2][0]);
        uint32_t bbase_l = (uint32_t)__cvta_generic_to_shared(&smem[s][3][0]);

        uint32_t Bh8[8], Bl8[8];
#pragma unroll
        for (int bj = 0; bj < 2; bj++) {
            ldmx4(&Bh8[4 * bj], frag_addr(bbase_h, wc * 32 + bj * 16, lane));
            ldmx4(&Bl8[4 * bj], frag_addr(bbase_l, wc * 32 + bj * 16, lane));
        }
#pragma unroll
        for (int fi = 0; fi < 4; fi++) {
            uint32_t Ah4[4], Al4[4];
            ldmx4(Ah4, frag_addr(abase_h, wr * 64 + fi * 16, lane));
            ldmx4(Al4, frag_addr(abase_l, wr * 64 + fi * 16, lane));
            // product-major: 4 independent accumulators between same-acc reuse
#pragma unroll
            for (int fj = 0; fj < 4; fj++) {
                int bj = fj >> 1, o = fj & 1;
                mma16816(acc[fi][fj], Ah4, Bh8[4 * bj + o], Bh8[4 * bj + 2 + o]);
            }
#pragma unroll
            for (int fj = 0; fj < 4; fj++) {
                int bj = fj >> 1, o = fj & 1;
                mma16816(acc[fi][fj], Ah4, Bl8[4 * bj + o], Bl8[4 * bj + 2 + o]);
            }
#pragma unroll
            for (int fj = 0; fj < 4; fj++) {
                int bj = fj >> 1, o = fj & 1;
                mma16816(acc[fi][fj], Al4, Bh8[4 * bj + o], Bh8[4 * bj + 2 + o]);
            }
        }

        // store prefetched stage kc+1 into the other buffer; safe because the
        // trailing sync of iter kc-1 guaranteed everyone left that buffer.
        if (kc + 1 < NC) {
#pragma unroll
            for (int t = 0; t < 4; t++)
                *(uint4*)(&smem[s ^ 1][t][0] + ldst) = pref[t];
        }
        __syncthreads();
    }

    // ------------------------- epilogue -------------------------
    int g = lane >> 2, t = lane & 3;

    if (MODE == 2) {
        float sc = sqrtf(g_norm[b]);
        float* outb = outF + (size_t)b * TRIU_LEN;
#pragma unroll
        for (int fi = 0; fi < 4; fi++) {
#pragma unroll
            for (int fj = 0; fj < 4; fj++) {
                int gi0 = ti0 + wr * 64 + fi * 16 + g;
                int gj0 = tj0 + wc * 32 + fj * 8 + 2 * t;
#pragma unroll
                for (int h = 0; h < 2; h++) {
                    int gi = gi0 + h * 8;
                    int rowbase = gi * C_DIM - (gi * (gi - 1)) / 2 - gi;
                    float v0 = acc[fi][fj][2 * h] * sc;
                    float v1 = acc[fi][fj][2 * h + 1] * sc;
                    if (gj0 >= gi)     outb[rowbase + gj0]     = v0;
                    if (gj0 + 1 >= gi) outb[rowbase + gj0 + 1] = v1;
                }
            }
        }
        return;
    }

    const float* mub = g_mu + b * C_DIM;
    float rn = (MODE == 3) ? (1.0f / g_norm[b]) : 0.f;
    __half* Cl = Ch + PLANE;
    __half* Zh = g_Z2 + (size_t)b * 2 * PLANE;   // MODE 3 second output
    __half* Zl = Zh + PLANE;

#pragma unroll
    for (int fi = 0; fi < 4; fi++) {
#pragma unroll
        for (int fj = 0; fj < 4; fj++) {
            int gi0 = ti0 + wr * 64 + fi * 16 + g;
            int gj0 = tj0 + wc * 32 + fj * 8 + 2 * t;
#pragma unroll
            for (int h = 0; h < 2; h++) {
                int gi = gi0 + h * 8;
                float r0 = acc[fi][fj][2 * h], r1 = acc[fi][fj][2 * h + 1];
                if (MODE == 3) {
                    float mi = mub[gi];
                    float v0 = (r0 * (1.0f / M_DIM) - mi * mub[gj0])     * rn;
                    float v1 = (r1 * (1.0f / M_DIM) - mi * mub[gj0 + 1]) * rn;
                    float z0 = (gi == gj0     ? 1.5f : 0.0f) - 0.5f * v0;
                    float z1 = (gi == gj0 + 1 ? 1.5f : 0.0f) - 0.5f * v1;
                    __half vh0, vl0, vh1, vl1, zh0, zl0, zh1, zl1;
                    split1(v0, vh0, vl0); split1(v1, vh1, vl1);
                    split1(z0, zh0, zl0); split1(z1, zh1, zl1);
                    *(uint32_t*)&Ch[gi * C_DIM + gj0] = packh(vh0, vh1);
                    *(uint32_t*)&Cl[gi * C_DIM + gj0] = packh(vl0, vl1);
                    *(uint32_t*)&Zh[gi * C_DIM + gj0] = packh(zh0, zh1);
                    *(uint32_t*)&Zl[gi * C_DIM + gj0] = packh(zl0, zl1);
                    if (mirror) {
                        Ch[gj0 * C_DIM + gi] = vh0; Cl[gj0 * C_DIM + gi] = vl0;
                        Ch[(gj0 + 1) * C_DIM + gi] = vh1; Cl[(gj0 + 1) * C_DIM + gi] = vl1;
                        Zh[gj0 * C_DIM + gi] = zh0; Zl[gj0 * C_DIM + gi] = zl0;
                        Zh[(gj0 + 1) * C_DIM + gi] = zh1; Zl[(gj0 + 1) * C_DIM + gi] = zl1;
                    }
                } else {
                    float v0 = (MODE == 1) ? ((gi == gj0     ? 1.5f : 0.0f) - 0.5f * r0) : r0;
                    float v1 = (MODE == 1) ? ((gi == gj0 + 1 ? 1.5f : 0.0f) - 0.5f * r1) : r1;
                    __half h0, l0, h1, l1;
                    split1(v0, h0, l0); split1(v1, h1, l1);
                    *(uint32_t*)&Ch[gi * C_DIM + gj0] = packh(h0, h1);
                    *(uint32_t*)&Cl[gi * C_DIM + gj0] = packh(l0, l1);
                    if (mirror) {
                        Ch[gj0 * C_DIM + gi] = h0; Cl[gj0 * C_DIM + gi] = l0;
                        Ch[(gj0 + 1) * C_DIM + gi] = h1; Cl[(gj0 + 1) * C_DIM + gi] = l1;
                    }
                }
            }
        }
    }
}

// ---------------------------------------------------------------------------
// Kernels (symmetric 3-tile grid: bx 0=(0,0), 1=(0,1) mirrored, 2=(1,1))
// ---------------------------------------------------------------------------
__global__ __launch_bounds__(256) void cov_kernel() {
    int bx = blockIdx.x, b = blockIdx.z;
    int ti0 = (bx == 2) ? 128 : 0;
    int tj0 = (bx >= 1) ? 128 : 0;
    const __half* Xh = g_X2 + (size_t)b * 2 * XPLANE;
    const __half* Xl = Xh + XPLANE;
    gemm_core<3, 13>(Xh + (size_t)ti0 * XCOLS, Xl + (size_t)ti0 * XCOLS,
                     Xh + (size_t)tj0 * XCOLS, Xl + (size_t)tj0 * XCOLS,
                     XCOLS,
                     g_A2 + (size_t)b * 2 * PLANE, nullptr,
                     b, ti0, tj0, bx == 1);
}

template <int MODE>
__global__ __launch_bounds__(256) void ns_gemm(const __half* __restrict__ A,
                                               const __half* __restrict__ B,
                                               __half* __restrict__ C,
                                               float* __restrict__ outF) {
    int bx = blockIdx.x, b = blockIdx.z;
    int ti0 = (bx == 2) ? 128 : 0;
    int tj0 = (bx >= 1) ? 128 : 0;
    const __half* Ah = A + (size_t)b * 2 * PLANE + (size_t)ti0 * C_DIM;
    const __half* Bh = B + (size_t)b * 2 * PLANE + (size_t)tj0 * C_DIM;
    gemm_core<MODE, 16>(Ah, Ah + PLANE, Bh, Bh + PLANE, C_DIM,
                        (MODE == 2) ? nullptr : C + (size_t)b * 2 * PLANE, outF,
                        b, ti0, tj0, bx == 1);
}

__global__ __launch_bounds__(256) void ns_gemm_dual(
    const __half* __restrict__ A1, const __half* __restrict__ B1, __half* __restrict__ C1,
    const __half* __restrict__ A2, const __half* __restrict__ B2, __half* __restrict__ C2) {
    int bx = blockIdx.x, b = blockIdx.z;
    int ti0 = (bx == 2) ? 128 : 0;
    int tj0 = (bx >= 1) ? 128 : 0;
    const __half* A = (blockIdx.y == 0) ? A1 : A2;
    const __half* B = (blockIdx.y == 0) ? B1 : B2;
    __half* C = (blockIdx.y == 0) ? C1 : C2;
    const __half* Ah = A + (size_t)b * 2 * PLANE + (size_t)ti0 * C_DIM;
    const __half* Bh = B + (size_t)b * 2 * PLANE + (size_t)tj0 * C_DIM;
    gemm_core<0, 16>(Ah, Ah + PLANE, Bh, Bh + PLANE, C_DIM,
                     C + (size_t)b * 2 * PLANE, nullptr, b, ti0, tj0, bx == 1);
}

// ---------------------------------------------------------------------------
// Launch: Newton-Schulz (ITER_N = 3)
//   ZY0 = 1.5I - 0.5 Ahat; Y1 = Ahat@ZY0; Z1 = ZY0
//   ZY1 = 1.5I - 0.5 Z1@Y1; Y2 = Y1@ZY1; Z2 = ZY1@Z1
//   E   = 1.5I - 0.5 Z2@Y2; out = triu((Y2@E)*sqrt(normA))
// ---------------------------------------------------------------------------
extern "C" void kernel_launch(void* const* d_in, const int* in_sizes, int n_in,
                              void* d_out, int out_size) {
    const float* x = (const float*)d_in[0];
    float* out = (float*)d_out;

    __half *A2, *Y2, *Z2, *ZY2, *T2;
    cudaGetSymbolAddress((void**)&A2,  g_A2);
    cudaGetSymbolAddress((void**)&Y2,  g_Y2);
    cudaGetSymbolAddress((void**)&Z2,  g_Z2);
    cudaGetSymbolAddress((void**)&ZY2, g_ZY2);
    cudaGetSymbolAddress((void**)&T2,  g_T2);

    dim3 grid(3, 1, BATCH), grid2(3, 2, BATCH);

    stats_kernel<<<BATCH, C_DIM>>>(x);
    split_x_kernel<<<BATCH * 256 / 8, 256>>>(x);
    cov_kernel<<<grid, 256>>>();                         // g_A2 = Ahat, g_Z2 = ZY0
    ns_gemm<0><<<grid, 256>>>(A2, Z2, Y2, nullptr);      // Y1 = Ahat @ ZY0
    ns_gemm<1><<<grid, 256>>>(Z2, Y2, ZY2, nullptr);     // ZY1 = 1.5I - 0.5 Z1@Y1
    ns_gemm_dual<<<grid2, 256>>>(Y2, ZY2, A2,            // Y2 = Y1 @ ZY1
                                 ZY2, Z2, T2);           // Z2 = ZY1 @ Z1
    ns_gemm<1><<<grid, 256>>>(T2, A2, ZY2, nullptr);     // E = 1.5I - 0.5 Z2@Y2
    ns_gemm<2><<<grid, 256>>>(A2, ZY2, nullptr, out);    // out = triu((Y2@E)*sqrt)
}